// round 15
// baseline (speedup 1.0000x reference)
#include <cuda_runtime.h>
#include <cstdint>

__device__ double g_accum = 0.0;
__device__ unsigned int g_done_count = 0;

__device__ __forceinline__ unsigned long long mk_evict_last_policy() {
    unsigned long long pol;
    asm volatile("createpolicy.fractional.L2::evict_last.b64 %0, 1.0;" : "=l"(pol));
    return pol;
}
__device__ __forceinline__ float4 ldg_persist4(const float4* p, unsigned long long pol) {
    float4 v;
    asm volatile("ld.global.L2::cache_hint.v4.f32 {%0,%1,%2,%3}, [%4], %5;"
                 : "=f"(v.x), "=f"(v.y), "=f"(v.z), "=f"(v.w)
                 : "l"(p), "l"(pol));
    return v;
}
// sm_103a 256-bit load: 8 consecutive f32 per lane (32B-aligned)
__device__ __forceinline__ void ldg_persist8(const float* p, unsigned long long pol,
                                             float4& lo, float4& hi) {
    asm volatile("ld.global.L2::cache_hint.v8.f32 "
                 "{%0,%1,%2,%3,%4,%5,%6,%7}, [%8], %9;"
                 : "=f"(lo.x), "=f"(lo.y), "=f"(lo.z), "=f"(lo.w),
                   "=f"(hi.x), "=f"(hi.y), "=f"(hi.z), "=f"(hi.w)
                 : "l"(p), "l"(pol));
}
__device__ __forceinline__ int ldg_persist_s32(const int* p, unsigned long long pol) {
    int v;
    asm volatile("ld.global.L2::cache_hint.s32 %0, [%1], %2;"
                 : "=r"(v) : "l"(p), "l"(pol));
    return v;
}
__device__ __forceinline__ long long ldg_persist_s64(const long long* p, unsigned long long pol) {
    long long v;
    asm volatile("ld.global.L2::cache_hint.s64 %0, [%1], %2;"
                 : "=l"(v) : "l"(p), "l"(pol));
    return v;
}

__device__ __forceinline__ float fma4(float4 a, float4 b, float acc) {
    return fmaf(a.x, b.x, fmaf(a.y, b.y, fmaf(a.z, b.z, fmaf(a.w, b.w, acc))));
}

// R14 structure + LDG.256: one warp per row, transposed mapping across 148
// SMs, evict_last everywhere, speculative dual-width label load, 2x LDG.256
// per phase, smem block reduce -> one double atomicAdd -> counter tail.
__global__ void __launch_bounds__(896, 1)
center_loss_fused(const float* __restrict__ x,
                  const float* __restrict__ centers,
                  const int* __restrict__ labels_raw,
                  float* __restrict__ out,
                  int B, int D, int C) {
    const int lane = threadIdx.x & 31;
    const int warp_in_blk = threadIdx.x >> 5;
    const int warps_per_blk = blockDim.x >> 5;
    const int nwarps = gridDim.x * warps_per_blk;
    const int n4 = D >> 2;

    const unsigned long long pol = mk_evict_last_policy();

    // dtype probe once per warp (independent of everything below)
    int nsample = B < 32 ? B : 32;
    int probe = (lane < nsample) ? ldg_persist_s32(labels_raw + 2 * lane + 1, pol) : 0;

    double local = 0.0;

    if (n4 == 128) {
        for (int row = warp_in_blk * gridDim.x + blockIdx.x; row < B; row += nwarps) {
            // phase 0: all independent loads back-to-back (speculative labels
            // + two 256-bit x loads; lane covers 8 consecutive floats)
            int cand32 = ldg_persist_s32(labels_raw + row, pol);
            long long cand64 = ldg_persist_s64((const long long*)labels_raw + row, pol);
            const float* __restrict__ xr = x + (size_t)row * D;
            float4 a0, a1, a2, a3;
            ldg_persist8(xr + lane * 8, pol, a0, a1);          // elems [0,256)
            ldg_persist8(xr + 256 + lane * 8, pol, a2, a3);    // elems [256,512)

            // phase 1: resolve label dtype while x streams in
            unsigned any = __ballot_sync(0xFFFFFFFFu, probe != 0);
            long long li = (any == 0) ? cand64 : (long long)cand32;
            if (li < 0) li = 0;
            if (li >= C) li = C - 1;

            // phase 2: two 256-bit center loads back-to-back
            const float* __restrict__ cr = centers + (size_t)li * D;
            float4 b0, b1, b2, b3;
            ldg_persist8(cr + lane * 8, pol, b0, b1);
            ldg_persist8(cr + 256 + lane * 8, pol, b2, b3);

            // x-norm overlaps the center round-trip
            float xsq = 0.f;
            xsq = fma4(a0, a0, xsq);
            xsq = fma4(a1, a1, xsq);
            xsq = fma4(a2, a2, xsq);
            xsq = fma4(a3, a3, xsq);

            float dot = 0.f, csq = 0.f;
            dot = fma4(a0, b0, dot);  csq = fma4(b0, b0, csq);
            dot = fma4(a1, b1, dot);  csq = fma4(b1, b1, csq);
            dot = fma4(a2, b2, dot);  csq = fma4(b2, b2, csq);
            dot = fma4(a3, b3, dot);  csq = fma4(b3, b3, csq);

            float v = fmaf(0.3f, dot, 0.5f * (xsq + csq));
            #pragma unroll
            for (int o = 16; o > 0; o >>= 1)
                v += __shfl_down_sync(0xFFFFFFFFu, v, o);
            if (lane == 0) {
                v = fminf(fmaxf(v, 1e-12f), 1e12f);
                local += (double)v;
            }
        }
    } else {
        unsigned any0 = __ballot_sync(0xFFFFFFFFu, probe != 0);
        const int is64 = (any0 == 0);
        for (int row = warp_in_blk * gridDim.x + blockIdx.x; row < B; row += nwarps) {
            long long li = is64 ? ((const long long*)labels_raw)[row]
                                : (long long)labels_raw[row];
            if (li < 0) li = 0;
            if (li >= C) li = C - 1;
            const float4* xr = reinterpret_cast<const float4*>(x + (size_t)row * D);
            const float4* cr = reinterpret_cast<const float4*>(centers + (size_t)li * D);
            float dot = 0.f, xsq = 0.f, csq = 0.f;
            for (int i = lane; i < n4; i += 32) {
                float4 a = ldg_persist4(xr + i, pol);
                float4 b = ldg_persist4(cr + i, pol);
                dot = fma4(a, b, dot);
                xsq = fma4(a, a, xsq);
                csq = fma4(b, b, csq);
            }
            float v = fmaf(0.3f, dot, 0.5f * (xsq + csq));
            #pragma unroll
            for (int o = 16; o > 0; o >>= 1)
                v += __shfl_down_sync(0xFFFFFFFFu, v, o);
            if (lane == 0) {
                v = fminf(fmaxf(v, 1e-12f), 1e12f);
                local += (double)v;
            }
        }
    }

    // ---- block partial -> single global double atomic ----
    __shared__ double sdata[32];
    if (lane == 0) sdata[warp_in_blk] = local;
    __syncthreads();
    if (warp_in_blk == 0) {
        double s = (lane < warps_per_blk) ? sdata[lane] : 0.0;
        #pragma unroll
        for (int o = 16; o > 0; o >>= 1)
            s += __shfl_down_sync(0xFFFFFFFFu, s, o);
        if (lane == 0) atomicAdd(&g_accum, s);
    }

    // ---- last block finalizes: one load, one store ----
    __shared__ bool s_last;
    __threadfence();
    if (threadIdx.x == 0) {
        unsigned int prev = atomicAdd(&g_done_count, 1u);
        s_last = (prev == gridDim.x - 1);
    }
    __syncthreads();
    if (s_last && threadIdx.x == 0) {
        double acc = atomicAdd(&g_accum, 0.0);      // coherent read at L2
        double masked_zeros = ((double)B * (double)C - (double)B) * 1e-12;
        out[0] = (float)((acc + masked_zeros) / (double)B);
        g_accum = 0.0;                               // reset for graph replay
        __threadfence();
        g_done_count = 0;
    }
}

extern "C" void kernel_launch(void* const* d_in, const int* in_sizes, int n_in,
                              void* d_out, int out_size) {
    const float* x = (const float*)d_in[0];
    const float* centers = (const float*)d_in[1];
    const int* labels = (const int*)d_in[2];
    float* out = (float*)d_out;

    const int B = in_sizes[2];
    const int D = in_sizes[0] / B;
    const int C = in_sizes[1] / D;

    const int threads = 896;   // 28 warps, 1 CTA per SM
    const int blocks = 148;    // one per SM; transposed row mapping inside
    center_loss_fused<<<blocks, threads>>>(x, centers, labels, out, B, D, C);
}